// round 7
// baseline (speedup 1.0000x reference)
#include <cuda_runtime.h>
#include <cuda_bf16.h>

// Problem constants (fixed): B=8, T=128, U=64, V=512
#define Bc  8
#define Tc  128
#define Uc  64
#define U1c 65
#define Vc  512
#define NEGV  -1e30f
#define LOG2E 1.4426950408889634f
#define LN2F  0.6931471805599453f

// ------------------------------------------------------------------
// Scratch (device globals)
// ------------------------------------------------------------------
__device__ __align__(16) float g_expP[Bc * U1c * Vc];
__device__ float g_Mu[Bc * U1c];
__device__ float g_pb0[Bc * U1c];
__device__ float g_plab[Bc * Uc];
__device__ __align__(16) float g_BL[Bc * Tc * U1c];  // blank lp, LOG2 domain
__device__ __align__(16) float g_LB[Bc * Tc * U1c];  // label lp, LOG2 domain (col 64 unused)
__device__ float g_cost[Bc];
__device__ unsigned int g_ticket;     // zero-init; reset each run

__device__ __forceinline__ float ex2a(float x)
{ float y; asm("ex2.approx.ftz.f32 %0, %1;" : "=f"(y) : "f"(x)); return y; }
__device__ __forceinline__ float lg2a(float x)
{ float y; asm("lg2.approx.ftz.f32 %0, %1;" : "=f"(y) : "f"(x)); return y; }

__device__ __forceinline__ float lse2(float x, float y)   // log2 domain
{
    float m = fmaxf(x, y);
    return m + lg2a(1.0f + ex2a(-fabsf(x - y)));
}

// ------------------------------------------------------------------
// K1: pred rows: rowmax + exp(x-max), Mu/pb0/plab gathers
// ------------------------------------------------------------------
__global__ void k_prep_pred(const float* __restrict__ pred,
                            const int*   __restrict__ labels)
{
    int idx = blockIdx.x;                  // [0, Bc*U1c)
    const float* row = pred + (size_t)idx * Vc;
    float* erow = g_expP + (size_t)idx * Vc;

    int tid = threadIdx.x;                 // 128 threads, 4 floats each
    float4 v = ((const float4*)row)[tid];

    float m = fmaxf(fmaxf(v.x, v.y), fmaxf(v.z, v.w));
#pragma unroll
    for (int o = 16; o; o >>= 1)
        m = fmaxf(m, __shfl_xor_sync(0xffffffffu, m, o));

    __shared__ float sm[4];
    if ((tid & 31) == 0) sm[tid >> 5] = m;
    __syncthreads();
    m = fmaxf(fmaxf(sm[0], sm[1]), fmaxf(sm[2], sm[3]));

    float4 e;
    e.x = __expf(v.x - m);
    e.y = __expf(v.y - m);
    e.z = __expf(v.z - m);
    e.w = __expf(v.w - m);
    ((float4*)erow)[tid] = e;

    if (tid == 0) {
        g_Mu[idx]  = m;
        g_pb0[idx] = v.x;                  // row[0]
        int b = idx / U1c, u = idx % U1c;
        if (u < Uc) {
            int l = labels[b * Uc + u];
            g_plab[b * Uc + u] = row[l];
        }
    }
}

// ------------------------------------------------------------------
// K2: joint -> BL/LB tables. Grid (Tc/2, Bc, 2), 256 threads, 4KB smem.
//  Phase A: exp of this block's 2 trans rows into smem.
//  Phase B: warp w (z-half) privately owns 4(+1) u columns; dot +
//           warp shuffle reduce; lanes 0/1 emit BL/LB. No barriers.
// ------------------------------------------------------------------
__global__ void __launch_bounds__(256)
k_joint(const float* __restrict__ trans,
        const int*   __restrict__ labels,
        const int*   __restrict__ label_lens)
{
    __shared__ float sexp[2 * Vc];         // 4 KB
    __shared__ float sMu[U1c], spb0[U1c], splab[Uc];
    __shared__ int   slab[Uc];
    __shared__ float wmax[8], sMt[2], stb0[2];
    __shared__ int   sUlen;

    int b   = blockIdx.y;
    int t0  = blockIdx.x * 2;
    int z   = blockIdx.z;                  // u-half
    int tid = threadIdx.x;
    int lane = tid & 31, w = tid >> 5;

    // ---------------- Phase A ----------------
    int r = tid >> 7;                      // t-row 0..1
    int j = tid & 127;                     // float4 index within row
    const float* trow = trans + ((size_t)(b * Tc + t0 + r)) * Vc;
    float4 v = ((const float4*)trow)[j];

    float m = fmaxf(fmaxf(v.x, v.y), fmaxf(v.z, v.w));
#pragma unroll
    for (int o = 16; o; o >>= 1)
        m = fmaxf(m, __shfl_xor_sync(0xffffffffu, m, o));
    if (lane == 0) wmax[w] = m;

    if (tid < U1c) { sMu[tid] = g_Mu[b * U1c + tid]; spb0[tid] = g_pb0[b * U1c + tid]; }
    if (tid >= 128 && tid < 128 + Uc) splab[tid - 128] = g_plab[b * Uc + (tid - 128)];
    if (tid >= 192 && tid < 192 + Uc) slab[tid - 192]  = labels[b * Uc + (tid - 192)];
    if (tid == 0) sUlen = label_lens[b];
    __syncthreads();

    m = fmaxf(fmaxf(wmax[4 * r], wmax[4 * r + 1]),
              fmaxf(wmax[4 * r + 2], wmax[4 * r + 3]));
    float4 e;
    e.x = __expf(v.x - m); e.y = __expf(v.y - m);
    e.z = __expf(v.z - m); e.w = __expf(v.w - m);
    ((float4*)sexp)[r * 128 + j] = e;
    if (j == 0) { sMt[r] = m; stb0[r] = v.x; }
    __syncthreads();

    // ---------------- Phase B ----------------
    float4 a[8];
#pragma unroll
    for (int k = 0; k < 4; ++k) {
        a[k]     = ((const float4*)sexp)[lane + 32 * k];
        a[4 + k] = ((const float4*)sexp)[128 + lane + 32 * k];
    }

    const float4* P = (const float4*)(g_expP + (size_t)b * U1c * Vc);
    int nu = (w == 0 && z == 1) ? 5 : 4;   // i=4 -> u=64
    int ubase = w + 32 * z;
    int u = ubase;
    float4 p0 = P[u * 128 + lane],       p1 = P[u * 128 + lane + 32],
           p2 = P[u * 128 + lane + 64],  p3 = P[u * 128 + lane + 96];

    for (int i = 0; i < nu; ++i) {
        float4 q0 = p0, q1 = p1, q2 = p2, q3 = p3;
        int un = (i + 1 < 4) ? (ubase + 8 * (i + 1)) : 64;
        if (i + 1 < nu) {
            p0 = P[un * 128 + lane];      p1 = P[un * 128 + lane + 32];
            p2 = P[un * 128 + lane + 64]; p3 = P[un * 128 + lane + 96];
        }

        float s0 = a[0].x*q0.x + a[0].y*q0.y + a[0].z*q0.z + a[0].w*q0.w
                 + a[1].x*q1.x + a[1].y*q1.y + a[1].z*q1.z + a[1].w*q1.w
                 + a[2].x*q2.x + a[2].y*q2.y + a[2].z*q2.z + a[2].w*q2.w
                 + a[3].x*q3.x + a[3].y*q3.y + a[3].z*q3.z + a[3].w*q3.w;
        float s1 = a[4].x*q0.x + a[4].y*q0.y + a[4].z*q0.z + a[4].w*q0.w
                 + a[5].x*q1.x + a[5].y*q1.y + a[5].z*q1.z + a[5].w*q1.w
                 + a[6].x*q2.x + a[6].y*q2.y + a[6].z*q2.z + a[6].w*q2.w
                 + a[7].x*q3.x + a[7].y*q3.y + a[7].z*q3.z + a[7].w*q3.w;

#pragma unroll
        for (int o = 16; o; o >>= 1) {
            s0 += __shfl_xor_sync(0xffffffffu, s0, o);
            s1 += __shfl_xor_sync(0xffffffffu, s1, o);
        }
        if (lane < 2) {
            float S = (lane == 0) ? s0 : s1;
            int t = t0 + lane;
            float logZ = sMt[lane] + sMu[u] + __logf(S);
            g_BL[((size_t)(b * Tc + t)) * U1c + u]
                = (stb0[lane] + spb0[u] - logZ) * LOG2E;
            if (u < Uc) {
                float lv = NEGV;
                if (u < sUlen) {
                    int l = slab[u];
                    float traw = __logf(sexp[lane * Vc + l]) + sMt[lane];
                    lv = (traw + splab[u] - logZ) * LOG2E;
                }
                g_LB[((size_t)(b * Tc + t)) * U1c + u] = lv;
            }
        }
        u = un;
    }
}

// ------------------------------------------------------------------
// K3: alpha DP. 8 blocks (one per b), 256 threads, 66.5 KB smem.
// Cooperative table load, then single-warp systolic with INTERLEAVED
// column ownership: lane L owns u = {L, L+32}; lane 0 also u = 64.
// Cross-lane chain per step = ONE lse2 (rotation shfl).
// ------------------------------------------------------------------
__global__ void __launch_bounds__(256)
k_dp(const int* __restrict__ act_lens,
     const int* __restrict__ label_lens,
     float*     __restrict__ out)
{
    extern __shared__ float smem[];
    float* sBL = smem;                     // [Tc][65]
    float* sLB = smem + Tc * U1c;          // [Tc][65]

    int b = blockIdx.x;
    int tid = threadIdx.x;

    const float4* BLg = (const float4*)(g_BL + (size_t)b * Tc * U1c);
    const float4* LBg = (const float4*)(g_LB + (size_t)b * Tc * U1c);
    for (int i = tid; i < (Tc * U1c) / 4; i += 256) ((float4*)sBL)[i] = BLg[i];
    for (int i = tid; i < (Tc * U1c) / 4; i += 256) ((float4*)sLB)[i] = LBg[i];
    float lastBL = g_BL[(size_t)b * Tc * U1c + Tc * U1c - 1]; // element 8320-1 handled by f4? 8320%4==0 -> covered
    (void)lastBL;
    __syncthreads();
    if (tid >= 32) return;

    int L = tid;
    int tlen = act_lens[b];
    int ulen = label_lens[b];
    int u2 = L + 32;

    float v1 = 0.0f, v2 = 0.0f, v3 = 0.0f;
    float cost = 0.0f;
    bool  have = false;

    int kmax = (tlen - 1) + ulen;          // last step that can matter
    int src = (L + 31) & 31;

    for (int k = 0; k <= kmax; ++k) {
        float r1 = __shfl_sync(0xffffffffu, v1, src);  // left col for set 1 / seed for set 2 (lane 0)
        float r2 = __shfl_sync(0xffffffffu, v2, src);  // left col for set 2 / seed for col 64 (lane 0)

        int t1 = k - L;
        if (t1 >= 0 && t1 < Tc) {
            if (t1 == 0) {
                v1 = (L == 0) ? 0.0f : r1 + sLB[L - 1];
            } else {
                float below = v1 + sBL[(t1 - 1) * U1c + L];
                v1 = (L == 0) ? below
                              : lse2(below, r1 + sLB[t1 * U1c + (L - 1)]);
            }
            if (t1 == tlen - 1 && ulen == L) { cost = v1 + sBL[t1 * U1c + L]; have = true; }
        }

        int t2 = t1 - 32;
        if (t2 >= 0 && t2 < Tc) {
            float left2 = (L == 0) ? r1 : r2;          // lane0: lane31's v1 (u=31)
            if (t2 == 0) {
                v2 = left2 + sLB[u2 - 1];
            } else {
                v2 = lse2(v2 + sBL[(t2 - 1) * U1c + u2],
                          left2 + sLB[t2 * U1c + (u2 - 1)]);
            }
            if (t2 == tlen - 1 && ulen == u2) { cost = v2 + sBL[t2 * U1c + u2]; have = true; }
        }

        if (L == 0) {
            int t3 = k - 64;
            if (t3 >= 0 && t3 < Tc) {
                float left3 = r2;                       // lane31's v2 (u=63)
                if (t3 == 0) {
                    v3 = left3 + sLB[63];
                } else {
                    v3 = lse2(v3 + sBL[(t3 - 1) * U1c + 64],
                              left3 + sLB[t3 * U1c + 63]);
                }
                if (t3 == tlen - 1 && ulen == 64) { cost = v3 + sBL[t3 * U1c + 64]; have = true; }
            }
        }
    }

    if (have) {
        g_cost[b] = -cost * LN2F;
        __threadfence();
        unsigned int old = atomicAdd(&g_ticket, 1u);
        if (old == Bc - 1) {
            __threadfence();
            float s = 0.0f;
#pragma unroll
            for (int i = 0; i < Bc; ++i) s += g_cost[i];
            out[0] = s;
            atomicExch(&g_ticket, 0u);     // reset for next graph replay
        }
    }
}

// ------------------------------------------------------------------
extern "C" void kernel_launch(void* const* d_in, const int* in_sizes, int n_in,
                              void* d_out, int out_size)
{
    const float* trans      = (const float*)d_in[0];
    const float* pred       = (const float*)d_in[1];
    const int*   labels     = (const int*)  d_in[2];
    const int*   act_lens   = (const int*)  d_in[3];
    const int*   label_lens = (const int*)  d_in[4];
    float* out = (float*)d_out;

    const int dpSmem = 2 * Tc * U1c * sizeof(float);    // 66560 B
    cudaFuncSetAttribute(k_dp, cudaFuncAttributeMaxDynamicSharedMemorySize, dpSmem);

    k_prep_pred<<<Bc * U1c, 128>>>(pred, labels);
    k_joint<<<dim3(Tc / 2, Bc, 2), 256>>>(trans, labels, label_lens);
    k_dp<<<Bc, 256, dpSmem>>>(act_lens, label_lens, out);
}

// round 9
// speedup vs baseline: 1.0400x; 1.0400x over previous
#include <cuda_runtime.h>
#include <cuda_bf16.h>

// Problem constants (fixed): B=8, T=128, U=64, V=512
#define Bc  8
#define Tc  128
#define Uc  64
#define U1c 65
#define Vc  512
#define NEGV  -1e30f
#define LOG2E 1.4426950408889634f
#define LN2F  0.6931471805599453f

// ------------------------------------------------------------------
// Scratch (device globals)
// ------------------------------------------------------------------
__device__ __align__(16) float g_expP[Bc * U1c * Vc];
__device__ float g_Mu[Bc * U1c];
__device__ float g_pb0[Bc * U1c];
__device__ float g_plab[Bc * Uc];
__device__ __align__(16) float g_BL[Bc * Tc * U1c];  // blank lp, LOG2 domain
__device__ __align__(16) float g_LB[Bc * Tc * U1c];  // label lp, LOG2 domain (col 64 unused)
__device__ float g_cost[Bc];
__device__ unsigned int g_bcnt[Bc];   // zero-init; reset each run
__device__ unsigned int g_ticket;     // zero-init; reset each run

__device__ __forceinline__ float ex2a(float x)
{ float y; asm("ex2.approx.ftz.f32 %0, %1;" : "=f"(y) : "f"(x)); return y; }
__device__ __forceinline__ float lg2a(float x)
{ float y; asm("lg2.approx.ftz.f32 %0, %1;" : "=f"(y) : "f"(x)); return y; }

__device__ __forceinline__ float lse2(float x, float y)   // log2 domain
{
    float m = fmaxf(x, y);
    return m + lg2a(1.0f + ex2a(-fabsf(x - y)));
}

__device__ __forceinline__ unsigned long long f2fma(
    unsigned long long a, unsigned long long b, unsigned long long c)
{
    unsigned long long d;
    asm("fma.rn.f32x2 %0, %1, %2, %3;" : "=l"(d) : "l"(a), "l"(b), "l"(c));
    return d;
}
__device__ __forceinline__ float f2sum(unsigned long long a)
{
    unsigned int lo, hi;
    asm("mov.b64 {%0,%1}, %2;" : "=r"(lo), "=r"(hi) : "l"(a));
    return __uint_as_float(lo) + __uint_as_float(hi);
}

// ------------------------------------------------------------------
// K1: pred rows: rowmax + exp(x-max), Mu/pb0/plab gathers
// ------------------------------------------------------------------
__global__ void k_prep_pred(const float* __restrict__ pred,
                            const int*   __restrict__ labels)
{
    int idx = blockIdx.x;                  // [0, Bc*U1c)
    const float* row = pred + (size_t)idx * Vc;
    float* erow = g_expP + (size_t)idx * Vc;

    int tid = threadIdx.x;                 // 128 threads, 4 floats each
    float4 v = ((const float4*)row)[tid];

    float m = fmaxf(fmaxf(v.x, v.y), fmaxf(v.z, v.w));
#pragma unroll
    for (int o = 16; o; o >>= 1)
        m = fmaxf(m, __shfl_xor_sync(0xffffffffu, m, o));

    __shared__ float sm[4];
    if ((tid & 31) == 0) sm[tid >> 5] = m;
    __syncthreads();
    m = fmaxf(fmaxf(sm[0], sm[1]), fmaxf(sm[2], sm[3]));

    float4 e;
    e.x = __expf(v.x - m);
    e.y = __expf(v.y - m);
    e.z = __expf(v.z - m);
    e.w = __expf(v.w - m);
    ((float4*)erow)[tid] = e;

    if (tid == 0) {
        g_Mu[idx]  = m;
        g_pb0[idx] = v.x;                  // row[0]
        int b = idx / U1c, u = idx % U1c;
        if (u < Uc) {
            int l = labels[b * Uc + u];
            g_plab[b * Uc + u] = row[l];
        }
    }
}

// ------------------------------------------------------------------
// K2 (fused): joint + chained DP. Grid (Tc/4, Bc), 256 threads.
//  Phase A: exp of this block's 4 trans rows into dyn smem (8 KB).
//  Phase B: warp w owns u = {w, w+8, ...}; packed f32x2 dots, rows 0-1
//           in regs, rows 2-3 via LDS; shuffle reduce; lanes 0-3 emit.
//  Phase C: LAST block of batch b runs the interleaved systolic DP
//           (single warp, 1 lse2 per step on the cross-lane chain).
// ------------------------------------------------------------------
__global__ void __launch_bounds__(256)
k_main(const float* __restrict__ trans,
       const int*   __restrict__ labels,
       const int*   __restrict__ act_lens,
       const int*   __restrict__ label_lens,
       float*       __restrict__ out)
{
    extern __shared__ float dsmem[];       // A/B: sexp[4*512]; C: sBL/sLB
    __shared__ float sMu[U1c], spb0[U1c], splab[Uc];
    __shared__ int   slab[Uc];
    __shared__ float wmax[8], sMt[4], stb0[4];
    __shared__ int   sUlen, sLast;

    int b   = blockIdx.y;
    int t0  = blockIdx.x * 4;
    int tid = threadIdx.x;
    int lane = tid & 31, w = tid >> 5;

    // ---------------- Phase A: 4 trans rows -> exp in smem ----------------
    int r = tid >> 6;                      // t-row 0..3
    int j = tid & 63;                      // 2 float4 per thread
    const float* trow = trans + ((size_t)(b * Tc + t0 + r)) * Vc;
    float4 v0 = ((const float4*)trow)[2 * j];
    float4 v1 = ((const float4*)trow)[2 * j + 1];

    float m = fmaxf(fmaxf(fmaxf(v0.x, v0.y), fmaxf(v0.z, v0.w)),
                    fmaxf(fmaxf(v1.x, v1.y), fmaxf(v1.z, v1.w)));
#pragma unroll
    for (int o = 16; o; o >>= 1)
        m = fmaxf(m, __shfl_xor_sync(0xffffffffu, m, o));
    if (lane == 0) wmax[w] = m;

    if (tid < U1c) { sMu[tid] = g_Mu[b * U1c + tid]; spb0[tid] = g_pb0[b * U1c + tid]; }
    if (tid >= 128 && tid < 128 + Uc) splab[tid - 128] = g_plab[b * Uc + (tid - 128)];
    if (tid >= 192 && tid < 192 + Uc) slab[tid - 192]  = labels[b * Uc + (tid - 192)];
    if (tid == 0) sUlen = label_lens[b];
    __syncthreads();

    m = fmaxf(wmax[2 * r], wmax[2 * r + 1]);
    float4 e0, e1;
    e0.x = __expf(v0.x - m); e0.y = __expf(v0.y - m);
    e0.z = __expf(v0.z - m); e0.w = __expf(v0.w - m);
    e1.x = __expf(v1.x - m); e1.y = __expf(v1.y - m);
    e1.z = __expf(v1.z - m); e1.w = __expf(v1.w - m);
    ((float4*)dsmem)[r * 128 + 2 * j]     = e0;
    ((float4*)dsmem)[r * 128 + 2 * j + 1] = e1;
    if (j == 0) { sMt[r] = m; stb0[r] = v0.x; }
    __syncthreads();

    // ---------------- Phase B ----------------
    // rows 0-1 in registers as packed pairs; rows 2-3 read from smem per u
    ulonglong2 a01[8];
#pragma unroll
    for (int k = 0; k < 4; ++k) {
        a01[k]     = ((const ulonglong2*)dsmem)[lane + 32 * k];          // row 0
        a01[4 + k] = ((const ulonglong2*)dsmem)[128 + lane + 32 * k];    // row 1
    }
    const ulonglong2* S2 = ((const ulonglong2*)dsmem) + 256;             // row 2
    const ulonglong2* S3 = ((const ulonglong2*)dsmem) + 384;             // row 3

    const ulonglong2* P = (const ulonglong2*)(g_expP + (size_t)b * U1c * Vc);
    int nu = (w == 0) ? 9 : 8;             // warp0 also covers u=64
    int u  = w;
    ulonglong2 p0 = P[u * 128 + lane],       p1 = P[u * 128 + lane + 32],
               p2 = P[u * 128 + lane + 64],  p3 = P[u * 128 + lane + 96];

    for (int i = 0; i < nu; ++i) {
        ulonglong2 q[4] = { p0, p1, p2, p3 };
        int un = u + 8;
        if (i + 1 < nu) {
            p0 = P[un * 128 + lane];      p1 = P[un * 128 + lane + 32];
            p2 = P[un * 128 + lane + 64]; p3 = P[un * 128 + lane + 96];
        }

        unsigned long long acc0 = 0ull, acc1 = 0ull, acc2 = 0ull, acc3 = 0ull;
#pragma unroll
        for (int k = 0; k < 4; ++k) {
            ulonglong2 c2 = S2[lane + 32 * k];
            ulonglong2 c3 = S3[lane + 32 * k];
            acc0 = f2fma(a01[k].x, q[k].x, acc0);
            acc0 = f2fma(a01[k].y, q[k].y, acc0);
            acc1 = f2fma(a01[4 + k].x, q[k].x, acc1);
            acc1 = f2fma(a01[4 + k].y, q[k].y, acc1);
            acc2 = f2fma(c2.x, q[k].x, acc2);
            acc2 = f2fma(c2.y, q[k].y, acc2);
            acc3 = f2fma(c3.x, q[k].x, acc3);
            acc3 = f2fma(c3.y, q[k].y, acc3);
        }
        float s0 = f2sum(acc0), s1 = f2sum(acc1), s2 = f2sum(acc2), s3 = f2sum(acc3);

#pragma unroll
        for (int o = 16; o; o >>= 1) {
            s0 += __shfl_xor_sync(0xffffffffu, s0, o);
            s1 += __shfl_xor_sync(0xffffffffu, s1, o);
            s2 += __shfl_xor_sync(0xffffffffu, s2, o);
            s3 += __shfl_xor_sync(0xffffffffu, s3, o);
        }
        if (lane < 4) {
            float S = (lane == 0) ? s0 : (lane == 1) ? s1 : (lane == 2) ? s2 : s3;
            int t = t0 + lane;
            float logZ = sMt[lane] + sMu[u] + __logf(S);
            g_BL[((size_t)(b * Tc + t)) * U1c + u]
                = (stb0[lane] + spb0[u] - logZ) * LOG2E;
            if (u < Uc) {
                float lv = NEGV;
                if (u < sUlen) {
                    int l = slab[u];
                    float traw = __logf(dsmem[lane * Vc + l]) + sMt[lane];
                    lv = (traw + splab[u] - logZ) * LOG2E;
                }
                g_LB[((size_t)(b * Tc + t)) * U1c + u] = lv;
            }
        }
        u = un;
    }

    // ---------------- Phase C: last block of batch b runs the DP ----------------
    __threadfence();
    __syncthreads();
    if (tid == 0) {
        unsigned int old = atomicAdd(&g_bcnt[b], 1u);
        sLast = (old == (Tc / 4 - 1));
    }
    __syncthreads();
    if (!sLast) return;
    if (tid == 0) atomicExch(&g_bcnt[b], 0u);   // reset for next graph replay
    __threadfence();                             // acquire other blocks' BL/LB

    float* sBL = dsmem;                          // [Tc][65], log2 domain
    float* sLB = dsmem + Tc * U1c;               // [Tc][65], log2 domain
    {
        const float4* BLg = (const float4*)(g_BL + (size_t)b * Tc * U1c);
        const float4* LBg = (const float4*)(g_LB + (size_t)b * Tc * U1c);
        for (int i = tid; i < (Tc * U1c) / 4; i += 256) ((float4*)sBL)[i] = BLg[i];
        for (int i = tid; i < (Tc * U1c) / 4; i += 256) ((float4*)sLB)[i] = LBg[i];
    }
    __syncthreads();
    if (tid >= 32) return;

    // Interleaved ownership: lane L owns u = {L, L+32}; lane 0 also u = 64.
    int L = tid;
    int tlen = act_lens[b];
    int ulen = sUlen;
    int u2 = L + 32;

    float d1 = 0.0f, d2 = 0.0f, d3 = 0.0f;
    float cost = 0.0f;
    bool  have = false;

    int kmax = (tlen - 1) + ulen;
    int src = (L + 31) & 31;

    for (int k = 0; k <= kmax; ++k) {
        float r1 = __shfl_sync(0xffffffffu, d1, src);
        float r2 = __shfl_sync(0xffffffffu, d2, src);

        int t1 = k - L;
        if (t1 >= 0 && t1 < Tc) {
            if (t1 == 0) {
                d1 = (L == 0) ? 0.0f : r1 + sLB[L - 1];
            } else {
                float below = d1 + sBL[(t1 - 1) * U1c + L];
                d1 = (L == 0) ? below
                              : lse2(below, r1 + sLB[t1 * U1c + (L - 1)]);
            }
            if (t1 == tlen - 1 && ulen == L) { cost = d1 + sBL[t1 * U1c + L]; have = true; }
        }

        int t2 = t1 - 32;
        if (t2 >= 0 && t2 < Tc) {
            float left2 = (L == 0) ? r1 : r2;      // lane0: lane31's d1 (u=31)
            if (t2 == 0) {
                d2 = left2 + sLB[u2 - 1];
            } else {
                d2 = lse2(d2 + sBL[(t2 - 1) * U1c + u2],
                          left2 + sLB[t2 * U1c + (u2 - 1)]);
            }
            if (t2 == tlen - 1 && ulen == u2) { cost = d2 + sBL[t2 * U1c + u2]; have = true; }
        }

        if (L == 0) {
            int t3 = k - 64;
            if (t3 >= 0 && t3 < Tc) {
                float left3 = r2;                  // lane31's d2 (u=63)
                if (t3 == 0) {
                    d3 = left3 + sLB[63];
                } else {
                    d3 = lse2(d3 + sBL[(t3 - 1) * U1c + 64],
                              left3 + sLB[t3 * U1c + 63]);
                }
                if (t3 == tlen - 1 && ulen == 64) { cost = d3 + sBL[t3 * U1c + 64]; have = true; }
            }
        }
    }

    if (have) {
        g_cost[b] = -cost * LN2F;
        __threadfence();
        unsigned int old = atomicAdd(&g_ticket, 1u);
        if (old == Bc - 1) {
            __threadfence();
            float s = 0.0f;
#pragma unroll
            for (int i = 0; i < Bc; ++i) s += g_cost[i];
            out[0] = s;
            atomicExch(&g_ticket, 0u);     // reset for next graph replay
        }
    }
}

// ------------------------------------------------------------------
extern "C" void kernel_launch(void* const* d_in, const int* in_sizes, int n_in,
                              void* d_out, int out_size)
{
    const float* trans      = (const float*)d_in[0];
    const float* pred       = (const float*)d_in[1];
    const int*   labels     = (const int*)  d_in[2];
    const int*   act_lens   = (const int*)  d_in[3];
    const int*   label_lens = (const int*)  d_in[4];
    float* out = (float*)d_out;

    const int dynSmem = 2 * Tc * U1c * sizeof(float);   // 66560 B (phase C tables)
    cudaFuncSetAttribute(k_main, cudaFuncAttributeMaxDynamicSharedMemorySize, dynSmem);

    k_prep_pred<<<Bc * U1c, 128>>>(pred, labels);
    k_main<<<dim3(Tc / 4, Bc), 256, dynSmem>>>(trans, labels, act_lens, label_lens, out);
}

// round 10
// speedup vs baseline: 1.1928x; 1.1469x over previous
#include <cuda_runtime.h>
#include <cuda_bf16.h>

// Problem constants (fixed): B=8, T=128, U=64, V=512
#define Bc  8
#define Tc  128
#define Uc  64
#define U1c 65
#define Vc  512
#define BLS 66                 // BL row stride (66 = 2 mod 32 -> conflict-free DP)
#define NEGV  -1e30f
#define LOG2E 1.4426950408889634f
#define LN2F  0.6931471805599453f

// ------------------------------------------------------------------
// Scratch (device globals)
// ------------------------------------------------------------------
__device__ __align__(16) float g_expP[Bc * U1c * Vc];
__device__ float g_Mu[Bc * U1c];
__device__ float g_pb0[Bc * U1c];
__device__ float g_plab[Bc * Uc];
__device__ __align__(16) float g_BL[Bc * Tc * BLS]; // blank lp, LOG2 domain, stride 66
__device__ __align__(16) float g_LB[Bc * Tc * Uc];  // label lp, LOG2 domain, stride 64
__device__ float g_cost[Bc];
__device__ unsigned int g_bcnt[Bc];   // zero-init; reset each run
__device__ unsigned int g_ticket;     // zero-init; reset each run

__device__ __forceinline__ float lse2(float x, float y)   // log2 domain
{
    float m = fmaxf(x, y);
    return m + __log2f(1.0f + exp2f(-fabsf(x - y)));
}

// ------------------------------------------------------------------
// K1: pred rows: rowmax + exp(x-max), Mu/pb0/plab gathers
// ------------------------------------------------------------------
__global__ void k_prep_pred(const float* __restrict__ pred,
                            const int*   __restrict__ labels)
{
    int idx = blockIdx.x;                  // [0, Bc*U1c)
    const float* row = pred + (size_t)idx * Vc;
    float* erow = g_expP + (size_t)idx * Vc;

    int tid = threadIdx.x;                 // 128 threads, 4 floats each
    float4 v = ((const float4*)row)[tid];

    float m = fmaxf(fmaxf(v.x, v.y), fmaxf(v.z, v.w));
#pragma unroll
    for (int o = 16; o; o >>= 1)
        m = fmaxf(m, __shfl_xor_sync(0xffffffffu, m, o));

    __shared__ float sm[4];
    if ((tid & 31) == 0) sm[tid >> 5] = m;
    __syncthreads();
    m = fmaxf(fmaxf(sm[0], sm[1]), fmaxf(sm[2], sm[3]));

    float4 e;
    e.x = __expf(v.x - m);
    e.y = __expf(v.y - m);
    e.z = __expf(v.z - m);
    e.w = __expf(v.w - m);
    ((float4*)erow)[tid] = e;

    if (tid == 0) {
        g_Mu[idx]  = m;
        g_pb0[idx] = v.x;                  // row[0]
        int b = idx / U1c, u = idx % U1c;
        if (u < Uc) {
            int l = labels[b * Uc + u];
            g_plab[b * Uc + u] = row[l];
        }
    }
}

// ------------------------------------------------------------------
// K2 (fused): joint + chained DP. Grid (Tc/4, Bc), 256 threads.
//  Phase A: exp of this block's 4 trans rows into dyn smem (8 KB).
//  Phase B: warp w owns u = {w, w+8, ...}; register-resident a[16],
//           plain FMA dots, shuffle reduce; lanes 0-3 emit BL/LB.
//  Phase C: LAST block of batch b runs the interleaved systolic DP
//           (single warp, one lse2 on the cross-lane chain, zero
//           bank conflicts with BL stride 66 / LB stride 64).
// ------------------------------------------------------------------
__global__ void __launch_bounds__(256)
k_main(const float* __restrict__ trans,
       const int*   __restrict__ labels,
       const int*   __restrict__ act_lens,
       const int*   __restrict__ label_lens,
       float*       __restrict__ out)
{
    extern __shared__ float dsmem[];       // A/B: sexp[4*512]; C: sBL/sLB
    __shared__ float sMu[U1c], spb0[U1c], splab[Uc];
    __shared__ int   slab[Uc];
    __shared__ float wmax[8], sMt[4], stb0[4];
    __shared__ int   sUlen, sLast;

    int b   = blockIdx.y;
    int t0  = blockIdx.x * 4;
    int tid = threadIdx.x;
    int lane = tid & 31, w = tid >> 5;

    // ---------------- Phase A: 4 trans rows -> exp in smem ----------------
    int r = tid >> 6;                      // t-row 0..3
    int j = tid & 63;                      // 2 float4 per thread
    const float* trow = trans + ((size_t)(b * Tc + t0 + r)) * Vc;
    float4 v0 = ((const float4*)trow)[2 * j];
    float4 v1 = ((const float4*)trow)[2 * j + 1];

    float m = fmaxf(fmaxf(fmaxf(v0.x, v0.y), fmaxf(v0.z, v0.w)),
                    fmaxf(fmaxf(v1.x, v1.y), fmaxf(v1.z, v1.w)));
#pragma unroll
    for (int o = 16; o; o >>= 1)
        m = fmaxf(m, __shfl_xor_sync(0xffffffffu, m, o));
    if (lane == 0) wmax[w] = m;

    if (tid < U1c) { sMu[tid] = g_Mu[b * U1c + tid]; spb0[tid] = g_pb0[b * U1c + tid]; }
    if (tid >= 128 && tid < 128 + Uc) splab[tid - 128] = g_plab[b * Uc + (tid - 128)];
    if (tid >= 192 && tid < 192 + Uc) slab[tid - 192]  = labels[b * Uc + (tid - 192)];
    if (tid == 0) sUlen = label_lens[b];
    __syncthreads();

    m = fmaxf(wmax[2 * r], wmax[2 * r + 1]);
    float4 e0, e1;
    e0.x = __expf(v0.x - m); e0.y = __expf(v0.y - m);
    e0.z = __expf(v0.z - m); e0.w = __expf(v0.w - m);
    e1.x = __expf(v1.x - m); e1.y = __expf(v1.y - m);
    e1.z = __expf(v1.z - m); e1.w = __expf(v1.w - m);
    ((float4*)dsmem)[r * 128 + 2 * j]     = e0;
    ((float4*)dsmem)[r * 128 + 2 * j + 1] = e1;
    if (j == 0) { sMt[r] = m; stb0[r] = v0.x; }
    __syncthreads();

    // ---------------- Phase B: warp-private u columns ----------------
    // a regs: 4 rows x 16 floats (element 4*(lane+32k)+m)
    float4 a[16];
#pragma unroll
    for (int jr = 0; jr < 4; ++jr)
#pragma unroll
        for (int k = 0; k < 4; ++k)
            a[jr * 4 + k] = ((const float4*)dsmem)[jr * 128 + lane + 32 * k];

    const float4* P = (const float4*)(g_expP + (size_t)b * U1c * Vc);
    int nu = (w == 0) ? 9 : 8;             // warp0 also covers u=64
    int u  = w;
    float4 p0 = P[u * 128 + lane],       p1 = P[u * 128 + lane + 32],
           p2 = P[u * 128 + lane + 64],  p3 = P[u * 128 + lane + 96];

    for (int i = 0; i < nu; ++i) {
        float4 q0 = p0, q1 = p1, q2 = p2, q3 = p3;
        int un = u + 8;
        if (i + 1 < nu) {
            p0 = P[un * 128 + lane];      p1 = P[un * 128 + lane + 32];
            p2 = P[un * 128 + lane + 64]; p3 = P[un * 128 + lane + 96];
        }

        float s0 = a[0].x*q0.x + a[0].y*q0.y + a[0].z*q0.z + a[0].w*q0.w
                 + a[1].x*q1.x + a[1].y*q1.y + a[1].z*q1.z + a[1].w*q1.w
                 + a[2].x*q2.x + a[2].y*q2.y + a[2].z*q2.z + a[2].w*q2.w
                 + a[3].x*q3.x + a[3].y*q3.y + a[3].z*q3.z + a[3].w*q3.w;
        float s1 = a[4].x*q0.x + a[4].y*q0.y + a[4].z*q0.z + a[4].w*q0.w
                 + a[5].x*q1.x + a[5].y*q1.y + a[5].z*q1.z + a[5].w*q1.w
                 + a[6].x*q2.x + a[6].y*q2.y + a[6].z*q2.z + a[6].w*q2.w
                 + a[7].x*q3.x + a[7].y*q3.y + a[7].z*q3.z + a[7].w*q3.w;
        float s2 = a[8].x*q0.x + a[8].y*q0.y + a[8].z*q0.z + a[8].w*q0.w
                 + a[9].x*q1.x + a[9].y*q1.y + a[9].z*q1.z + a[9].w*q1.w
                 + a[10].x*q2.x + a[10].y*q2.y + a[10].z*q2.z + a[10].w*q2.w
                 + a[11].x*q3.x + a[11].y*q3.y + a[11].z*q3.z + a[11].w*q3.w;
        float s3 = a[12].x*q0.x + a[12].y*q0.y + a[12].z*q0.z + a[12].w*q0.w
                 + a[13].x*q1.x + a[13].y*q1.y + a[13].z*q1.z + a[13].w*q1.w
                 + a[14].x*q2.x + a[14].y*q2.y + a[14].z*q2.z + a[14].w*q2.w
                 + a[15].x*q3.x + a[15].y*q3.y + a[15].z*q3.z + a[15].w*q3.w;

#pragma unroll
        for (int o = 16; o; o >>= 1) {
            s0 += __shfl_xor_sync(0xffffffffu, s0, o);
            s1 += __shfl_xor_sync(0xffffffffu, s1, o);
            s2 += __shfl_xor_sync(0xffffffffu, s2, o);
            s3 += __shfl_xor_sync(0xffffffffu, s3, o);
        }
        if (lane < 4) {
            float S = (lane == 0) ? s0 : (lane == 1) ? s1 : (lane == 2) ? s2 : s3;
            int t = t0 + lane;
            float logZ = sMt[lane] + sMu[u] + __logf(S);
            g_BL[((size_t)(b * Tc + t)) * BLS + u]
                = (stb0[lane] + spb0[u] - logZ) * LOG2E;
            if (u < Uc) {
                float lv = NEGV;
                if (u < sUlen) {
                    int l = slab[u];
                    float traw = __logf(dsmem[lane * Vc + l]) + sMt[lane];
                    lv = (traw + splab[u] - logZ) * LOG2E;
                }
                g_LB[((size_t)(b * Tc + t)) * Uc + u] = lv;
            }
        }
        u = un;
    }

    // ---------------- Phase C: last block of batch b runs the DP ----------------
    __threadfence();
    __syncthreads();
    if (tid == 0) {
        unsigned int old = atomicAdd(&g_bcnt[b], 1u);
        sLast = (old == (Tc / 4 - 1));
    }
    __syncthreads();
    if (!sLast) return;
    if (tid == 0) atomicExch(&g_bcnt[b], 0u);   // reset for next graph replay
    __threadfence();                             // acquire other blocks' BL/LB

    float* sBL = dsmem;                          // [Tc][66], log2 domain
    float* sLB = dsmem + Tc * BLS;               // [Tc][64], log2 domain
    {
        const float4* BLg = (const float4*)(g_BL + (size_t)b * Tc * BLS);
        const float4* LBg = (const float4*)(g_LB + (size_t)b * Tc * Uc);
        for (int i = tid; i < (Tc * BLS) / 4; i += 256) ((float4*)sBL)[i] = BLg[i];
        for (int i = tid; i < (Tc * Uc) / 4;  i += 256) ((float4*)sLB)[i] = LBg[i];
    }
    __syncthreads();
    if (tid >= 32) return;

    // Interleaved ownership: lane L owns u = {L, L+32}; lane 0 also u = 64.
    int L = tid;
    int tlen = act_lens[b];
    int ulen = sUlen;
    int u2 = L + 32;

    float d1 = 0.0f, d2 = 0.0f, d3 = 0.0f;
    float cost = 0.0f;
    bool  have = false;

    int kmax = (tlen - 1) + ulen;
    int src = (L + 31) & 31;

    for (int k = 0; k <= kmax; ++k) {
        float r1 = __shfl_sync(0xffffffffu, d1, src);
        float r2 = __shfl_sync(0xffffffffu, d2, src);

        int t1 = k - L;
        if (t1 >= 0 && t1 < Tc) {
            if (t1 == 0) {
                d1 = (L == 0) ? 0.0f : r1 + sLB[L - 1];
            } else {
                float below = d1 + sBL[(t1 - 1) * BLS + L];
                d1 = (L == 0) ? below
                              : lse2(below, r1 + sLB[t1 * Uc + (L - 1)]);
            }
            if (t1 == tlen - 1 && ulen == L) { cost = d1 + sBL[t1 * BLS + L]; have = true; }
        }

        int t2 = t1 - 32;
        if (t2 >= 0 && t2 < Tc) {
            float left2 = (L == 0) ? r1 : r2;      // lane0: lane31's d1 (u=31)
            if (t2 == 0) {
                d2 = left2 + sLB[u2 - 1];
            } else {
                d2 = lse2(d2 + sBL[(t2 - 1) * BLS + u2],
                          left2 + sLB[t2 * Uc + (u2 - 1)]);
            }
            if (t2 == tlen - 1 && ulen == u2) { cost = d2 + sBL[t2 * BLS + u2]; have = true; }
        }

        if (L == 0) {
            int t3 = k - 64;
            if (t3 >= 0 && t3 < Tc) {
                float left3 = r2;                  // lane31's d2 (u=63)
                if (t3 == 0) {
                    d3 = left3 + sLB[63];
                } else {
                    d3 = lse2(d3 + sBL[(t3 - 1) * BLS + 64],
                              left3 + sLB[t3 * Uc + 63]);
                }
                if (t3 == tlen - 1 && ulen == 64) { cost = d3 + sBL[t3 * BLS + 64]; have = true; }
            }
        }
    }

    if (have) {
        g_cost[b] = -cost * LN2F;
        __threadfence();
        unsigned int old = atomicAdd(&g_ticket, 1u);
        if (old == Bc - 1) {
            __threadfence();
            float s = 0.0f;
#pragma unroll
            for (int i = 0; i < Bc; ++i) s += g_cost[i];
            out[0] = s;
            atomicExch(&g_ticket, 0u);     // reset for next graph replay
        }
    }
}

// ------------------------------------------------------------------
extern "C" void kernel_launch(void* const* d_in, const int* in_sizes, int n_in,
                              void* d_out, int out_size)
{
    const float* trans      = (const float*)d_in[0];
    const float* pred       = (const float*)d_in[1];
    const int*   labels     = (const int*)  d_in[2];
    const int*   act_lens   = (const int*)  d_in[3];
    const int*   label_lens = (const int*)  d_in[4];
    float* out = (float*)d_out;

    const int dynSmem = (Tc * BLS + Tc * Uc) * sizeof(float);  // 66560 B
    cudaFuncSetAttribute(k_main, cudaFuncAttributeMaxDynamicSharedMemorySize, dynSmem);

    k_prep_pred<<<Bc * U1c, 128>>>(pred, labels);
    k_main<<<dim3(Tc / 4, Bc), 256, dynSmem>>>(trans, labels, act_lens, label_lens, out);
}

// round 11
// speedup vs baseline: 1.7113x; 1.4347x over previous
#include <cuda_runtime.h>
#include <cuda_bf16.h>

// Problem constants (fixed): B=8, T=128, U=64, V=512
#define Bc  8
#define Tc  128
#define Uc  64
#define U1c 65
#define Vc  512
#define NEGV  -1e30f
#define LOG2E 1.4426950408889634f
#define LN2F  0.6931471805599453f

// ------------------------------------------------------------------
// Scratch (device globals; no allocation allowed)
// ------------------------------------------------------------------
__device__ __align__(16) float g_expP[Bc * U1c * Vc];
__device__ float g_Mu[Bc * U1c];
__device__ float g_pb0[Bc * U1c];
__device__ float g_plab[Bc * Uc];
__device__ __align__(16) float g_BL[Bc * Tc * U1c];  // blank lp, LOG2 domain
__device__ __align__(16) float g_LB[Bc * Tc * Uc];   // label lp, LOG2 domain
__device__ float g_cost[Bc];
__device__ unsigned int g_bcnt[Bc];   // zero-init; reset each run
__device__ unsigned int g_ticket;     // zero-init; reset each run

__device__ __forceinline__ float laddexp2(float x, float y)
{
    float m = fmaxf(x, y);
    float d = fabsf(x - y);
    return m + __log2f(1.0f + exp2f(-d));
}

// ------------------------------------------------------------------
// K1: pred rows only: rowmax + exp(x-max), Mu/pb0/plab gathers
// ------------------------------------------------------------------
__global__ void k_prep_pred(const float* __restrict__ pred,
                            const int*   __restrict__ labels)
{
    int idx = blockIdx.x;                  // [0, Bc*U1c)
    const float* row = pred + (size_t)idx * Vc;
    float* erow = g_expP + (size_t)idx * Vc;

    int tid = threadIdx.x;                 // 128 threads, 4 floats each
    float4 v = ((const float4*)row)[tid];

    float m = fmaxf(fmaxf(v.x, v.y), fmaxf(v.z, v.w));
#pragma unroll
    for (int o = 16; o; o >>= 1)
        m = fmaxf(m, __shfl_xor_sync(0xffffffffu, m, o));

    __shared__ float sm[4];
    if ((tid & 31) == 0) sm[tid >> 5] = m;
    __syncthreads();
    m = fmaxf(fmaxf(sm[0], sm[1]), fmaxf(sm[2], sm[3]));

    float4 e;
    e.x = __expf(v.x - m);
    e.y = __expf(v.y - m);
    e.z = __expf(v.z - m);
    e.w = __expf(v.w - m);
    ((float4*)erow)[tid] = e;

    if (tid == 0) {
        g_Mu[idx]  = m;
        g_pb0[idx] = v.x;                  // row[0]
        int b = idx / U1c, u = idx % U1c;
        if (u < Uc) {
            int l = labels[b * Uc + u];
            g_plab[b * Uc + u] = row[l];
        }
    }
}

// ------------------------------------------------------------------
// K2 (fused): joint + chained DP.
// Grid (Tc/4, Bc), 256 threads.
//  Phase A: block computes exp of its 4 trans rows into dyn smem.
//  Phase B: each warp privately owns 8 u-columns -> BL/LB (no barriers).
//  Phase C: the LAST block of batch b runs the full alpha DP for b
//           (single-warp systolic, zero barriers) + final batch sum.
// ------------------------------------------------------------------
__global__ void __launch_bounds__(256)
k_main(const float* __restrict__ trans,
       const int*   __restrict__ labels,
       const int*   __restrict__ act_lens,
       const int*   __restrict__ label_lens,
       float*       __restrict__ out)
{
    extern __shared__ float dsmem[];       // phase A/B: sexp[4*512]; phase C: sBL/sLB
    __shared__ float sMu[U1c], spb0[U1c], splab[Uc];
    __shared__ int   slab[Uc];
    __shared__ float wmax[8], sMt[4], stb0[4];
    __shared__ int   sUlen, sLast;

    int b   = blockIdx.y;
    int t0  = blockIdx.x * 4;
    int tid = threadIdx.x;
    int lane = tid & 31, w = tid >> 5;

    // ---------------- Phase A: trans rows -> exp in smem ----------------
    int r = tid >> 6;                      // t-row 0..3
    int j = tid & 63;                      // 8 elems each
    const float* trow = trans + ((size_t)(b * Tc + t0 + r)) * Vc;
    float4 v0 = ((const float4*)trow)[2 * j];
    float4 v1 = ((const float4*)trow)[2 * j + 1];

    float m = fmaxf(fmaxf(fmaxf(v0.x, v0.y), fmaxf(v0.z, v0.w)),
                    fmaxf(fmaxf(v1.x, v1.y), fmaxf(v1.z, v1.w)));
#pragma unroll
    for (int o = 16; o; o >>= 1)
        m = fmaxf(m, __shfl_xor_sync(0xffffffffu, m, o));
    if (lane == 0) wmax[w] = m;

    // per-b small arrays (independent of wmax sync)
    if (tid < U1c) { sMu[tid] = g_Mu[b * U1c + tid]; spb0[tid] = g_pb0[b * U1c + tid]; }
    if (tid < Uc)  { splab[tid] = g_plab[b * Uc + tid]; slab[tid] = labels[b * Uc + tid]; }
    if (tid == 0)  sUlen = label_lens[b];
    __syncthreads();

    m = fmaxf(wmax[2 * r], wmax[2 * r + 1]);
    float4 e0, e1;
    e0.x = __expf(v0.x - m); e0.y = __expf(v0.y - m);
    e0.z = __expf(v0.z - m); e0.w = __expf(v0.w - m);
    e1.x = __expf(v1.x - m); e1.y = __expf(v1.y - m);
    e1.z = __expf(v1.z - m); e1.w = __expf(v1.w - m);
    ((float4*)dsmem)[r * 128 + 2 * j]     = e0;
    ((float4*)dsmem)[r * 128 + 2 * j + 1] = e1;
    if (j == 0) { sMt[r] = m; stb0[r] = v0.x; }
    __syncthreads();

    // ---------------- Phase B: warp-private u columns ----------------
    // a regs: 4 rows x 16 floats (element 4*(lane+32k)+m)
    float4 a[16];
#pragma unroll
    for (int jr = 0; jr < 4; ++jr)
#pragma unroll
        for (int k = 0; k < 4; ++k)
            a[jr * 4 + k] = ((const float4*)dsmem)[jr * 128 + lane + 32 * k];

    const float4* P = (const float4*)(g_expP + (size_t)b * U1c * Vc);
    int nu = (w == 0) ? 9 : 8;             // warp0 also covers u=64
    int u  = w;
    float4 p0 = P[u * 128 + lane],       p1 = P[u * 128 + lane + 32],
           p2 = P[u * 128 + lane + 64],  p3 = P[u * 128 + lane + 96];

    for (int i = 0; i < nu; ++i) {
        float4 q0 = p0, q1 = p1, q2 = p2, q3 = p3;
        int un = u + 8;
        if (i + 1 < nu) {
            p0 = P[un * 128 + lane];      p1 = P[un * 128 + lane + 32];
            p2 = P[un * 128 + lane + 64]; p3 = P[un * 128 + lane + 96];
        }

        float s0, s1, s2, s3;
        {
            s0 = a[0].x*q0.x + a[0].y*q0.y + a[0].z*q0.z + a[0].w*q0.w
               + a[1].x*q1.x + a[1].y*q1.y + a[1].z*q1.z + a[1].w*q1.w
               + a[2].x*q2.x + a[2].y*q2.y + a[2].z*q2.z + a[2].w*q2.w
               + a[3].x*q3.x + a[3].y*q3.y + a[3].z*q3.z + a[3].w*q3.w;
            s1 = a[4].x*q0.x + a[4].y*q0.y + a[4].z*q0.z + a[4].w*q0.w
               + a[5].x*q1.x + a[5].y*q1.y + a[5].z*q1.z + a[5].w*q1.w
               + a[6].x*q2.x + a[6].y*q2.y + a[6].z*q2.z + a[6].w*q2.w
               + a[7].x*q3.x + a[7].y*q3.y + a[7].z*q3.z + a[7].w*q3.w;
            s2 = a[8].x*q0.x + a[8].y*q0.y + a[8].z*q0.z + a[8].w*q0.w
               + a[9].x*q1.x + a[9].y*q1.y + a[9].z*q1.z + a[9].w*q1.w
               + a[10].x*q2.x + a[10].y*q2.y + a[10].z*q2.z + a[10].w*q2.w
               + a[11].x*q3.x + a[11].y*q3.y + a[11].z*q3.z + a[11].w*q3.w;
            s3 = a[12].x*q0.x + a[12].y*q0.y + a[12].z*q0.z + a[12].w*q0.w
               + a[13].x*q1.x + a[13].y*q1.y + a[13].z*q1.z + a[13].w*q1.w
               + a[14].x*q2.x + a[14].y*q2.y + a[14].z*q2.z + a[14].w*q2.w
               + a[15].x*q3.x + a[15].y*q3.y + a[15].z*q3.z + a[15].w*q3.w;
        }
#pragma unroll
        for (int o = 16; o; o >>= 1) {
            s0 += __shfl_xor_sync(0xffffffffu, s0, o);
            s1 += __shfl_xor_sync(0xffffffffu, s1, o);
            s2 += __shfl_xor_sync(0xffffffffu, s2, o);
            s3 += __shfl_xor_sync(0xffffffffu, s3, o);
        }
        if (lane < 4) {
            float S = (lane == 0) ? s0 : (lane == 1) ? s1 : (lane == 2) ? s2 : s3;
            int t = t0 + lane;
            float logZ = sMt[lane] + sMu[u] + __logf(S);
            g_BL[((size_t)(b * Tc + t)) * U1c + u]
                = (stb0[lane] + spb0[u] - logZ) * LOG2E;
            if (u < Uc) {
                float lv = NEGV;
                if (u < sUlen) {
                    int l = slab[u];
                    float traw = __logf(dsmem[lane * Vc + l]) + sMt[lane];
                    lv = (traw + splab[u] - logZ) * LOG2E;
                }
                g_LB[((size_t)(b * Tc + t)) * Uc + u] = lv;
            }
        }
        u = un;
    }

    // ---------------- Phase C: last block of batch b runs the DP ----------------
    __threadfence();
    __syncthreads();
    if (tid == 0) {
        unsigned int old = atomicAdd(&g_bcnt[b], 1u);
        sLast = (old == 31u);
    }
    __syncthreads();
    if (!sLast) return;
    if (tid == 0) atomicExch(&g_bcnt[b], 0u);  // reset for next graph replay
    __threadfence();                            // acquire other blocks' BL/LB

    float* sBL = dsmem;                         // [Tc][U1c], log2 domain
    float* sLB = dsmem + Tc * U1c;              // [Tc][Uc],  log2 domain
    {
        const float4* BLg = (const float4*)(g_BL + (size_t)b * Tc * U1c);
        const float4* LBg = (const float4*)(g_LB + (size_t)b * Tc * Uc);
        for (int i = tid; i < (Tc * U1c) / 4; i += 256) ((float4*)sBL)[i] = BLg[i];
        for (int i = tid; i < (Tc * Uc) / 4;  i += 256) ((float4*)sLB)[i] = LBg[i];
    }
    __syncthreads();
    if (tid >= 32) return;

    int L = tid;                                // lane owns u = {2L, 2L+1}; L==31 also u=64
    int tlen = act_lens[b];
    int ulen = label_lens[b];
    float vA = 0.0f, vB = 0.0f, vC = 0.0f;
    float cost = 0.0f;
    bool  have = false;
    int   uA = 2 * L, uB = 2 * L + 1;

    // The cost cell (t = tlen-1, u = ulen) is produced at step
    // k = (tlen-1) + L_t with L_t = min(31, ulen/2); later steps are dead.
    int Lt = ulen >> 1; if (Lt > 31) Lt = 31;
    int kmax = (tlen - 1) + Lt;

    for (int k = 0; k <= kmax; ++k) {
        float leftPrev = __shfl_up_sync(0xffffffffu, vB, 1); // lane L-1's u=2L-1 at our t
        int t = k - L;
        if (t >= 0 && t < Tc) {
            float nA, nB;
            if (t == 0) {
                nA = (L == 0) ? 0.0f : leftPrev + sLB[uA - 1];
                nB = nA + sLB[uB - 1];
            } else {
                float below = vA + sBL[(t - 1) * U1c + uA];
                nA = (L == 0) ? below
                              : laddexp2(below, leftPrev + sLB[t * Uc + uA - 1]);
                nB = laddexp2(vB + sBL[(t - 1) * U1c + uB],
                              nA + sLB[t * Uc + uB - 1]);
            }
            vA = nA; vB = nB;
            if (L == 31) {
                float nC = (t == 0) ? (nB + sLB[63])
                                    : laddexp2(vC + sBL[(t - 1) * U1c + 64],
                                               nB + sLB[t * Uc + 63]);
                vC = nC;
            }
            if (t == tlen - 1) {
                if (ulen == uA)                  { cost = vA + sBL[t * U1c + uA]; have = true; }
                else if (ulen == uB)             { cost = vB + sBL[t * U1c + uB]; have = true; }
                else if (L == 31 && ulen == 64)  { cost = vC + sBL[t * U1c + 64]; have = true; }
            }
        }
    }

    if (have) {
        g_cost[b] = -cost * LN2F;
        __threadfence();
        unsigned int old = atomicAdd(&g_ticket, 1u);
        if (old == Bc - 1) {
            __threadfence();
            float s = 0.0f;
#pragma unroll
            for (int i = 0; i < Bc; ++i) s += g_cost[i];
            out[0] = s;
            atomicExch(&g_ticket, 0u);          // reset for next graph replay
        }
    }
}

// ------------------------------------------------------------------
extern "C" void kernel_launch(void* const* d_in, const int* in_sizes, int n_in,
                              void* d_out, int out_size)
{
    const float* trans      = (const float*)d_in[0];
    const float* pred       = (const float*)d_in[1];
    const int*   labels     = (const int*)  d_in[2];
    const int*   act_lens   = (const int*)  d_in[3];
    const int*   label_lens = (const int*)  d_in[4];
    float* out = (float*)d_out;

    const int dynSmem = (Tc * U1c + Tc * Uc) * sizeof(float); // 66048 B
    cudaFuncSetAttribute(k_main, cudaFuncAttributeMaxDynamicSharedMemorySize, dynSmem);

    k_prep_pred<<<Bc * U1c, 128>>>(pred, labels);
    k_main<<<dim3(Tc / 4, Bc), 256, dynSmem>>>(trans, labels, act_lens, label_lens, out);
}